// round 12
// baseline (speedup 1.0000x reference)
#include <cuda_runtime.h>
#include <stdint.h>

// IN:  x (4, 64, 224, 224) fp32
// OUT: (4, 576, 223*223) fp32, plane ck = bc*9 + ki*3 + kj
// out[ck, oh*223+ow] = x[bc, oh+ki-1, ow+kj-1] (0 if OOB)
#define OSP   49729u      // 223*223
#define ISTR  50176u      // 224*224

__device__ __forceinline__ unsigned smem_u32(const void* p) {
    return (unsigned)__cvta_generic_to_shared(p);
}

// stage one 8-row chunk's 11 padded rows into buf via cp.async (zfill pads/OOB)
__device__ __forceinline__ void stage_chunk(float (*buf)[232],
                                            const float* __restrict__ xb,
                                            unsigned g8, unsigned tid) {
    // 11 rows x 58 f4 slots (slot 0 & 57 = pads -> zfill)
    for (unsigned f = tid; f < 638u; f += 288u) {
        unsigned sr = f / 58u;
        unsigned s  = f - 58u * sr;
        int ih = (int)g8 - 1 + (int)sr;
        bool ok = (s >= 1u && s <= 56u) && ((unsigned)ih < 224u);
        const float* src = xb + (size_t)(ok ? ih : 0) * 224u
                              + 4u * ((ok ? s : 1u) - 1u);
        unsigned dst = smem_u32(&buf[sr][4u * s]);
        unsigned n = ok ? 16u : 0u;   // src-size 0 => zero-fill
        asm volatile("cp.async.cg.shared.global [%0], [%1], 16, %2;"
                     :: "r"(dst), "l"(src), "r"(n));
    }
    asm volatile("cp.async.commit_group;");
}

__device__ __forceinline__ void write_chunk(const float (*sbuf)[232],
                                            float* __restrict__ out,
                                            unsigned g8, unsigned nrows,
                                            unsigned ck, unsigned ki,
                                            unsigned kj, unsigned lane) {
    for (unsigned r = 0; r < nrows; ++r) {
        unsigned oh   = g8 + r;
        size_t   drow = (size_t)ck * OSP + (size_t)oh * 223u;
        unsigned lead = (4u - ((unsigned)drow & 3u)) & 3u;
        unsigned tail = 3u - lead;
        unsigned sr   = r + ki;
        unsigned off  = lead + kj + 3u;     // padded-row idx of first body float
        unsigned dlt  = off & 3u;
        unsigned jb   = off >> 2u;
        const float4* sm4 = (const float4*)sbuf[sr];
        float4* dst4 = (float4*)(out + drow + lead);

        for (unsigned j = lane; j < 55u; j += 32u) {
            float4 a = sm4[jb + j];
            float4 b = sm4[jb + j + 1u];
            float4 v;
            switch (dlt) {
              case 0:  v = a; break;
              case 1:  v = make_float4(a.y, a.z, a.w, b.x); break;
              case 2:  v = make_float4(a.z, a.w, b.x, b.y); break;
              default: v = make_float4(a.w, b.x, b.y, b.z); break;
            }
            __stcs(dst4 + j, v);
        }

        // straddle float4 across row boundary (tail of oh + lead of oh+1)
        if (lane == 0u && tail != 0u && oh < 222u) {
            float vv[4];
#pragma unroll
            for (unsigned t = 0; t < 4u; ++t) {
                vv[t] = (t < tail) ? sbuf[sr][off + 220u + t]
                                   : sbuf[sr + 1u][(t - tail) + kj + 3u];
            }
            __stcs((float4*)(out + drow + lead + 220u),
                   make_float4(vv[0], vv[1], vv[2], vv[3]));
        }

        // plane-end tail scalars (oh == 222 only)
        if (oh == 222u && lane < tail) {
            __stcs(out + drow + lead + 220u + lane, sbuf[sr][off + 220u + lane]);
        }

        // plane-start head scalars (first row of plane only)
        if (g8 == 0u && r == 0u && lane < lead) {
            __stcs(out + drow + lane, sbuf[sr][lane + kj + 3u]);
        }
    }
}

// Block = (two 8-row chunks, bc). 9 warps = 9 (ki,kj) planes.
// Double-buffered cp.async pipeline: stage A, stage B, wait A, write A
// (B's loads in flight), wait B, write B.
__global__ void __launch_bounds__(288, 7) unfold_v12(const float* __restrict__ x,
                                                     float* __restrict__ out) {
    __shared__ __align__(16) float bufA[11][232];
    __shared__ __align__(16) float bufB[11][232];
    unsigned g8a = blockIdx.x * 16u;
    unsigned g8b = g8a + 8u;
    unsigned bc  = blockIdx.y;
    unsigned tid = threadIdx.x;
    unsigned w = tid >> 5, lane = tid & 31u;

    const float* xb = x + (size_t)bc * ISTR;
    stage_chunk(bufA, xb, g8a, tid);
    stage_chunk(bufB, xb, g8b, tid);

    unsigned ki = w / 3u;
    unsigned kj = w - 3u * ki;
    unsigned ck = bc * 9u + w;
    unsigned nrowsB = (g8b + 8u <= 223u) ? 8u : (223u - g8b);  // 8, last pair 7

    asm volatile("cp.async.wait_group 1;");
    __syncthreads();
    write_chunk(bufA, out, g8a, 8u, ck, ki, kj, lane);

    asm volatile("cp.async.wait_group 0;");
    __syncthreads();
    write_chunk(bufB, out, g8b, nrowsB, ck, ki, kj, lane);
}

extern "C" void kernel_launch(void* const* d_in, const int* in_sizes, int n_in,
                              void* d_out, int out_size) {
    const float* x = (const float*)d_in[0];
    float* out = (float*)d_out;
    dim3 grid(14, 256);   // 14 chunk-pairs (27*8 + 7 rows), 256 bc planes
    unfold_v12<<<grid, 288>>>(x, out);
}